// round 1
// baseline (speedup 1.0000x reference)
#include <cuda_runtime.h>
#include <cstdint>

// Problem constants (fixed by the dataset: N=32768, D=50, P=2)
constexpr int D    = 50;
constexpr int P1   = 3;      // p+1
constexpr int NB   = 1326;   // number of basis functions
constexpr int TPB  = 256;
constexpr int NBT  = (NB + TPB - 1) / TPB;  // 6 bases per thread
constexpr int ROWS = 8;      // rows of x per block

// Scratch: per-basis sparse term descriptors (d1, p1, d2, p2).
// Order <= 2 guarantees at most 2 nonzero entries per idxset row.
__device__ int4 g_terms[NB];

__global__ void pce_preprocess(const int* __restrict__ idxset) {
    int b = blockIdx.x * blockDim.x + threadIdx.x;
    if (b >= NB) return;
    int d1 = 0, o1 = 0, d2 = 0, o2 = 0, cnt = 0;
    #pragma unroll 5
    for (int d = 0; d < D; ++d) {
        int p = idxset[b * D + d];
        if (p > 0) {
            if (cnt == 0) { d1 = d; o1 = p; }
            else          { d2 = d; o2 = p; }
            ++cnt;
        }
    }
    // empty slots point at (d=0, p=0) -> pv0 == 1.0 (B[0] = [1,0,0])
    g_terms[b] = make_int4(d1, o1, d2, o2);
}

__global__ __launch_bounds__(TPB)
void pce_phi_kernel(const float* __restrict__ x,
                    const float* __restrict__ mean,
                    const float* __restrict__ var,
                    const float* __restrict__ Bc,   // oneDbasis, (3,3) row-major
                    float* __restrict__ out,
                    int N) {
    __shared__ float pv[P1][64];   // padded to 64 to keep banks clean

    // Cache this thread's basis term descriptors in registers.
    int4 t[NBT];
    #pragma unroll
    for (int i = 0; i < NBT; ++i) {
        int b = threadIdx.x + i * TPB;
        t[i] = (b < NB) ? g_terms[b] : make_int4(0, 0, 0, 0);
    }

    // Basis coefficients (broadcast loads, L1-resident).
    const float b00 = Bc[0], b01 = Bc[1], b02 = Bc[2];
    const float b10 = Bc[3], b11 = Bc[4], b12 = Bc[5];
    const float b20 = Bc[6], b21 = Bc[7], b22 = Bc[8];

    const int row0 = blockIdx.x * ROWS;
    const int tid  = threadIdx.x;

    for (int r = 0; r < ROWS; ++r) {
        int n = row0 + r;
        if (n >= N) break;

        __syncthreads();  // protect pv from previous iteration's readers
        if (tid < D) {
            float xn = (x[(size_t)n * D + tid] - mean[tid]) / var[tid];
            pv[0][tid] = b00 + xn * (b01 + xn * b02);
            pv[1][tid] = b10 + xn * (b11 + xn * b12);
            pv[2][tid] = b20 + xn * (b21 + xn * b22);
        }
        __syncthreads();

        float* __restrict__ orow = out + (size_t)n * NB;
        #pragma unroll
        for (int i = 0; i < NBT; ++i) {
            int b = tid + i * TPB;
            if (b < NB) {
                int4 ti = t[i];
                orow[b] = pv[ti.y][ti.x] * pv[ti.w][ti.z];
            }
        }
    }
}

extern "C" void kernel_launch(void* const* d_in, const int* in_sizes, int n_in,
                              void* d_out, int out_size) {
    const float* x       = (const float*)d_in[0];
    const float* mean    = (const float*)d_in[1];
    const float* var     = (const float*)d_in[2];
    const float* oneDb   = (const float*)d_in[3];
    const int*   idxset  = (const int*)  d_in[4];
    float*       out     = (float*)d_out;

    const int N = in_sizes[0] / D;  // 32768

    pce_preprocess<<<(NB + TPB - 1) / TPB, TPB>>>(idxset);

    int grid = (N + ROWS - 1) / ROWS;  // 4096 blocks
    pce_phi_kernel<<<grid, TPB>>>(x, mean, var, oneDb, out, N);
}

// round 2
// speedup vs baseline: 1.3631x; 1.3631x over previous
#include <cuda_runtime.h>
#include <cstdint>

// Problem constants (fixed by the dataset: N=32768, D=50, P=2)
constexpr int D    = 50;
constexpr int NB   = 1326;   // number of basis functions (order <= 2, D=50)
constexpr int TPB  = 256;
constexpr int RB   = 8;      // rows of x per block
constexpr int PVW  = 52;     // padded width of one pv order row
constexpr int PVR  = 3 * PVW;// floats per row in pv table (156)
constexpr int NF4  = RB * NB / 4;  // 2652 float4 per block chunk

// Packed per-basis term: low byte = o1*52+d1, high byte = o2*52+d2.
// Empty slots -> offset 0 (pv[order 0][dim 0] == B[0,0] == 1.0 multiplier... see note:
// order-0 poly is constant B[0,0]=1 for this basis, so (0,0) is the identity term).
__device__ uint16_t g_packed[NB];

__global__ void pce_preprocess(const int* __restrict__ idxset) {
    int b = blockIdx.x * blockDim.x + threadIdx.x;
    if (b >= NB) return;
    int off1 = 0, off2 = 0, cnt = 0;
    for (int d = 0; d < D; ++d) {
        int p = idxset[b * D + d];
        if (p > 0) {
            int off = p * PVW + d;
            if (cnt == 0) off1 = off; else off2 = off;
            ++cnt;
        }
    }
    g_packed[b] = (uint16_t)(off1 | (off2 << 8));
}

__global__ __launch_bounds__(TPB)
void pce_phi_kernel(const float* __restrict__ x,
                    const float* __restrict__ mean,
                    const float* __restrict__ var,
                    const float* __restrict__ Bc,   // oneDbasis (3,3) row-major
                    float* __restrict__ out,
                    int N) {
    __shared__ float    pv[RB * PVR];     // [row][order][dim], 4992 B
    __shared__ uint16_t st[NB];           // packed terms, 2652 B

    const int tid  = threadIdx.x;
    const int row0 = blockIdx.x * RB;

    // Stage packed term table into shared.
    for (int i = tid; i < NB; i += TPB) st[i] = g_packed[i];

    // Basis coefficients (broadcast, L1-resident).
    const float b00 = Bc[0], b01 = Bc[1], b02 = Bc[2];
    const float b10 = Bc[3], b11 = Bc[4], b12 = Bc[5];
    const float b20 = Bc[6], b21 = Bc[7], b22 = Bc[8];

    // Load all RB rows of x, normalize, evaluate all three polys.
    for (int i = tid; i < RB * D; i += TPB) {
        int r = i / D, d = i - r * D;
        int n = row0 + r;
        float xn = 0.0f;
        if (n < N) xn = (x[(size_t)n * D + d] - mean[d]) / var[d];
        float* p = pv + r * PVR + d;
        p[0 * PVW] = b00 + xn * (b01 + xn * b02);
        p[1 * PVW] = b10 + xn * (b11 + xn * b12);
        p[2 * PVW] = b20 + xn * (b21 + xn * b22);
    }
    __syncthreads();

    // Stream the whole RB x NB chunk as float4 stores.
    // Chunk byte base = blockIdx.x * RB*NB*4 = blockIdx.x * 42432, 16B-aligned.
    size_t base = (size_t)blockIdx.x * (RB * NB);
    float4* __restrict__ out4 = (float4*)(out + base);
    const size_t total_f = (size_t)N * NB;

    #pragma unroll 2
    for (int q = tid; q < NF4; q += TPB) {
        if (base + (size_t)q * 4 + 3 >= total_f) break;  // tail guard (unused for N=32768)
        float vals[4];
        #pragma unroll
        for (int e = 0; e < 4; ++e) {
            int v = q * 4 + e;
            int r = v / NB;          // const-div -> mul/shift
            int b = v - r * NB;
            unsigned t = st[b];
            const float* p = pv + r * PVR;
            vals[e] = p[t & 0xFFu] * p[t >> 8];
        }
        out4[q] = make_float4(vals[0], vals[1], vals[2], vals[3]);
    }
}

extern "C" void kernel_launch(void* const* d_in, const int* in_sizes, int n_in,
                              void* d_out, int out_size) {
    const float* x      = (const float*)d_in[0];
    const float* mean   = (const float*)d_in[1];
    const float* var    = (const float*)d_in[2];
    const float* oneDb  = (const float*)d_in[3];
    const int*   idxset = (const int*)  d_in[4];
    float*       out    = (float*)d_out;

    const int N = in_sizes[0] / D;  // 32768

    pce_preprocess<<<(NB + TPB - 1) / TPB, TPB>>>(idxset);

    int grid = (N + RB - 1) / RB;   // 4096 blocks
    pce_phi_kernel<<<grid, TPB>>>(x, mean, var, oneDb, out, N);
}

// round 3
// speedup vs baseline: 1.4132x; 1.0368x over previous
#include <cuda_runtime.h>
#include <cstdint>

// Problem constants (fixed by the dataset: N=32768, D=50, P=2)
constexpr int D     = 50;
constexpr int NB    = 1326;          // number of basis functions
constexpr int NPAIR = NB / 2;        // 663
constexpr int TPB   = 256;
constexpr int NSLOT = (NPAIR + TPB - 1) / TPB;  // 3 pair-slots per thread
constexpr int RB    = 8;             // rows of x per block
constexpr int PVW   = 52;            // padded width of one pv order row
constexpr int PVR   = 3 * PVW;       // floats per row in pv table (156)

// Packed per-pair term offsets: for bases (2q, 2q+1):
//   byte0 = off1(2q), byte1 = off2(2q), byte2 = off1(2q+1), byte3 = off2(2q+1)
// where off = order*PVW + dim (< 156 < 256). Empty slot -> 0 (pv[0][0] == 1).
__device__ uint32_t g_pairs[NPAIR];

__global__ void pce_preprocess(const int* __restrict__ idxset) {
    int q = blockIdx.x * blockDim.x + threadIdx.x;
    if (q >= NPAIR) return;
    uint32_t pk = 0;
    #pragma unroll
    for (int e = 0; e < 2; ++e) {
        int b = 2 * q + e;
        int off1 = 0, off2 = 0, cnt = 0;
        for (int d = 0; d < D; ++d) {
            int p = idxset[b * D + d];
            if (p > 0) {
                int off = p * PVW + d;
                if (cnt == 0) off1 = off; else off2 = off;
                ++cnt;
            }
        }
        pk |= (uint32_t)(off1 | (off2 << 8)) << (16 * e);
    }
    g_pairs[q] = pk;
}

__global__ __launch_bounds__(TPB)
void pce_phi_kernel(const float* __restrict__ x,
                    const float* __restrict__ mean,
                    const float* __restrict__ var,
                    const float* __restrict__ Bc,   // oneDbasis (3,3) row-major
                    float* __restrict__ out,
                    int N) {
    __shared__ float pv[RB * PVR];   // [row][order][dim], 4992 B

    const int tid  = threadIdx.x;
    const int row0 = blockIdx.x * RB;

    // Per-thread basis-pair term offsets -> registers (one LDG each).
    int oa0[NSLOT], ob0[NSLOT], oa1[NSLOT], ob1[NSLOT];
    bool act[NSLOT];
    #pragma unroll
    for (int i = 0; i < NSLOT; ++i) {
        int q = tid + i * TPB;
        act[i] = (q < NPAIR);
        uint32_t pk = act[i] ? g_pairs[q] : 0u;
        oa0[i] =  pk        & 0xFF;
        ob0[i] = (pk >> 8)  & 0xFF;
        oa1[i] = (pk >> 16) & 0xFF;
        ob1[i] = (pk >> 24);
    }

    // Basis coefficients (broadcast, L1-resident).
    const float b00 = Bc[0], b01 = Bc[1], b02 = Bc[2];
    const float b10 = Bc[3], b11 = Bc[4], b12 = Bc[5];
    const float b20 = Bc[6], b21 = Bc[7], b22 = Bc[8];

    // Load RB rows of x, normalize, evaluate all three polys into shared.
    for (int i = tid; i < RB * D; i += TPB) {
        int r = i / D, d = i - r * D;
        int n = row0 + r;
        float xn = 0.0f;
        if (n < N) xn = (x[(size_t)n * D + d] - mean[d]) / var[d];
        float* p = pv + r * PVR + d;
        p[0 * PVW] = b00 + xn * (b01 + xn * b02);
        p[1 * PVW] = b10 + xn * (b11 + xn * b12);
        p[2 * PVW] = b20 + xn * (b21 + xn * b22);
    }
    __syncthreads();

    // Stream output: fixed bases per thread, loop over rows, float2 stores.
    #pragma unroll
    for (int r = 0; r < RB; ++r) {
        int n = row0 + r;
        if (n >= N) break;                      // never taken for N=32768
        const float* __restrict__ p = pv + r * PVR;
        float* __restrict__ orow = out + (size_t)n * NB;
        #pragma unroll
        for (int i = 0; i < NSLOT; ++i) {
            if (act[i]) {
                int q = tid + i * TPB;
                float2 v;
                v.x = p[oa0[i]] * p[ob0[i]];
                v.y = p[oa1[i]] * p[ob1[i]];
                *reinterpret_cast<float2*>(orow + 2 * q) = v;
            }
        }
    }
}

extern "C" void kernel_launch(void* const* d_in, const int* in_sizes, int n_in,
                              void* d_out, int out_size) {
    const float* x      = (const float*)d_in[0];
    const float* mean   = (const float*)d_in[1];
    const float* var    = (const float*)d_in[2];
    const float* oneDb  = (const float*)d_in[3];
    const int*   idxset = (const int*)  d_in[4];
    float*       out    = (float*)d_out;

    const int N = in_sizes[0] / D;  // 32768

    pce_preprocess<<<(NPAIR + TPB - 1) / TPB, TPB>>>(idxset);

    int grid = (N + RB - 1) / RB;   // 4096 blocks
    pce_phi_kernel<<<grid, TPB>>>(x, mean, var, oneDb, out, N);
}

// round 4
// speedup vs baseline: 1.8357x; 1.2989x over previous
#include <cuda_runtime.h>
#include <cstdint>

// Problem constants (fixed by the dataset: N=32768, D=50, P=2)
constexpr int D     = 50;
constexpr int NB    = 1326;          // number of basis functions
constexpr int NPAIR = NB / 2;        // 663
constexpr int TPB   = 256;
constexpr int NSLOT = (NPAIR + TPB - 1) / TPB;  // 3 pair-slots per thread
constexpr int RB    = 16;            // rows of x per block
constexpr int PVW   = 52;            // padded width of one pv order row
constexpr int PVR   = 3 * PVW;       // floats per row in pv table (156)

// Per-basis packed term: low byte = off1, high byte = off2, off = order*PVW + dim.
// Empty slot -> 0 (pv[order0][dim0] == 1.0 since order-0 poly == B[0,0] == 1).
__device__ __align__(4) uint16_t g_packed[NB];

// One warp per basis: lanes cover dims {lane, lane+32}, ballot+shuffle extract
// the (at most 2) nonzero orders.
__global__ __launch_bounds__(32)
void pce_preprocess(const int* __restrict__ idxset) {
    const int b    = blockIdx.x;
    const int lane = threadIdx.x;

    int p0 = idxset[b * D + lane];                              // lane < 32 < D
    int p1 = (lane + 32 < D) ? idxset[b * D + lane + 32] : 0;
    int off0 = p0 * PVW + lane;
    int off1 = p1 * PVW + lane + 32;

    unsigned m0 = __ballot_sync(0xFFFFFFFFu, p0 != 0);
    unsigned m1 = __ballot_sync(0xFFFFFFFFu, p1 != 0);

    int offs[2] = {0, 0};
    int cnt = 0;
    unsigned m = m0;                       // m0/m1 uniform across the warp
    while (m && cnt < 2) {
        int l = __ffs(m) - 1;
        offs[cnt++] = __shfl_sync(0xFFFFFFFFu, off0, l);
        m &= m - 1;
    }
    m = m1;
    while (m && cnt < 2) {
        int l = __ffs(m) - 1;
        offs[cnt++] = __shfl_sync(0xFFFFFFFFu, off1, l);
        m &= m - 1;
    }
    if (lane == 0)
        g_packed[b] = (uint16_t)(offs[0] | (offs[1] << 8));
}

__global__ __launch_bounds__(TPB)
void pce_phi_kernel(const float* __restrict__ x,
                    const float* __restrict__ mean,
                    const float* __restrict__ var,
                    const float* __restrict__ Bc,   // oneDbasis (3,3) row-major
                    float* __restrict__ out,
                    int N) {
    __shared__ float pv[RB * PVR];   // [row][order][dim], 9984 B

    const int tid  = threadIdx.x;
    const int row0 = blockIdx.x * RB;

    // Per-thread basis-pair term offsets -> registers (one 32-bit LDG per pair).
    const uint32_t* __restrict__ pairs = reinterpret_cast<const uint32_t*>(g_packed);
    int oa0[NSLOT], ob0[NSLOT], oa1[NSLOT], ob1[NSLOT];
    bool act[NSLOT];
    #pragma unroll
    for (int i = 0; i < NSLOT; ++i) {
        int q = tid + i * TPB;
        act[i] = (q < NPAIR);
        uint32_t pk = act[i] ? pairs[q] : 0u;
        oa0[i] =  pk        & 0xFF;
        ob0[i] = (pk >> 8)  & 0xFF;
        oa1[i] = (pk >> 16) & 0xFF;
        ob1[i] = (pk >> 24);
    }

    // Basis coefficients (broadcast, L1-resident).
    const float b00 = Bc[0], b01 = Bc[1], b02 = Bc[2];
    const float b10 = Bc[3], b11 = Bc[4], b12 = Bc[5];
    const float b20 = Bc[6], b21 = Bc[7], b22 = Bc[8];

    // Load RB rows of x, normalize, evaluate all three polys into shared.
    for (int i = tid; i < RB * D; i += TPB) {
        int r = i / D, d = i - r * D;
        int n = row0 + r;
        float xn = 0.0f;
        if (n < N) xn = (x[(size_t)n * D + d] - mean[d]) / var[d];
        float* p = pv + r * PVR + d;
        p[0 * PVW] = b00 + xn * (b01 + xn * b02);
        p[1 * PVW] = b10 + xn * (b11 + xn * b12);
        p[2 * PVW] = b20 + xn * (b21 + xn * b22);
    }
    __syncthreads();

    // Stream output: fixed bases per thread, loop over rows, streaming float2 stores.
    #pragma unroll
    for (int r = 0; r < RB; ++r) {
        int n = row0 + r;
        if (n >= N) break;                      // never taken for N=32768
        const float* __restrict__ p = pv + r * PVR;
        float* __restrict__ orow = out + (size_t)n * NB;
        #pragma unroll
        for (int i = 0; i < NSLOT; ++i) {
            if (act[i]) {
                int q = tid + i * TPB;
                float2 v;
                v.x = p[oa0[i]] * p[ob0[i]];
                v.y = p[oa1[i]] * p[ob1[i]];
                __stcs(reinterpret_cast<float2*>(orow) + q, v);
            }
        }
    }
}

extern "C" void kernel_launch(void* const* d_in, const int* in_sizes, int n_in,
                              void* d_out, int out_size) {
    const float* x      = (const float*)d_in[0];
    const float* mean   = (const float*)d_in[1];
    const float* var    = (const float*)d_in[2];
    const float* oneDb  = (const float*)d_in[3];
    const int*   idxset = (const int*)  d_in[4];
    float*       out    = (float*)d_out;

    const int N = in_sizes[0] / D;  // 32768

    pce_preprocess<<<NB, 32>>>(idxset);

    int grid = (N + RB - 1) / RB;   // 2048 blocks
    pce_phi_kernel<<<grid, TPB>>>(x, mean, var, oneDb, out, N);
}